// round 3
// baseline (speedup 1.0000x reference)
#include <cuda_runtime.h>
#include <cuda_bf16.h>
#include <cstdint>

#define SMOOTH 0.1f
#define NROWS 4096
#define VOCAB 32000
#define DIM   1024
#define CTILES 250   /* VOCAB/128 */
#define RTILES 32    /* NROWS/128 */

// ---- scratch (static __device__: allocation-free per harness rules) ----
__device__ __nv_bfloat16 g_xb[(size_t)NROWS * DIM];      // 8 MB
__device__ __nv_bfloat16 g_Wb[(size_t)VOCAB * DIM];      // 64 MB
__device__ float g_pExp[(size_t)CTILES * NROWS];         // 4 MB
__device__ float g_pLog[(size_t)CTILES * NROWS];         // 4 MB
__device__ float g_ly[NROWS];
__device__ float g_rv[NROWS];

// ---------------- converts: f32 -> bf16 ----------------
__global__ void cvt_x_kernel(const float* __restrict__ s) {
    size_t i = ((size_t)blockIdx.x * blockDim.x + threadIdx.x) * 4;
    float4 v = *(const float4*)(s + i);
    __nv_bfloat162* d = reinterpret_cast<__nv_bfloat162*>(&g_xb[i]);
    d[0] = __floats2bfloat162_rn(v.x, v.y);
    d[1] = __floats2bfloat162_rn(v.z, v.w);
}
__global__ void cvt_w_kernel(const float* __restrict__ s) {
    size_t i = ((size_t)blockIdx.x * blockDim.x + threadIdx.x) * 4;
    float4 v = *(const float4*)(s + i);
    __nv_bfloat162* d = reinterpret_cast<__nv_bfloat162*>(&g_Wb[i]);
    d[0] = __floats2bfloat162_rn(v.x, v.y);
    d[1] = __floats2bfloat162_rn(v.z, v.w);
}

// ---------------- GEMM + fused LSE partials ----------------
__device__ __forceinline__ void cp16(void* sdst, const void* gsrc) {
    unsigned sa = (unsigned)__cvta_generic_to_shared(sdst);
    asm volatile("cp.async.cg.shared.global [%0], [%1], 16;\n" :: "r"(sa), "l"(gsrc));
}

__global__ void __launch_bounds__(256) gemm_lse_kernel() {
    constexpr int LDS = 40;  // 32 bf16 data + 8 bf16 pad -> 80B row stride, 16B aligned, bank-conflict-free
    __shared__ __align__(16) __nv_bfloat16 As[2][128 * LDS];
    __shared__ __align__(16) __nv_bfloat16 Bs[2][128 * LDS];
    __shared__ float redE[128][4];
    __shared__ float redL[128][4];

    const int tid  = threadIdx.x;
    const int lane = tid & 31;
    const int warp = tid >> 5;
    const int ct = blockIdx.x, rt = blockIdx.y;
    const int m0 = rt * 128, n0 = ct * 128;
    const int wm0 = (warp & 1) * 64;  // 2 warps in M
    const int wn  = warp >> 1;        // 4 warps in N
    const int wn0 = wn * 32;

    float c[4][4][4];
#pragma unroll
    for (int i = 0; i < 4; i++)
#pragma unroll
        for (int j = 0; j < 4; j++)
#pragma unroll
            for (int k = 0; k < 4; k++) c[i][j][k] = 0.f;

    auto load_stage = [&](int st, int k0) {
#pragma unroll
        for (int cc = tid; cc < 512; cc += 256) {
            int row = cc >> 2, col = (cc & 3) << 3;
            cp16(&As[st][row * LDS + col], &g_xb[(size_t)(m0 + row) * DIM + k0 + col]);
        }
#pragma unroll
        for (int cc = tid; cc < 512; cc += 256) {
            int row = cc >> 2, col = (cc & 3) << 3;
            cp16(&Bs[st][row * LDS + col], &g_Wb[(size_t)(n0 + row) * DIM + k0 + col]);
        }
        asm volatile("cp.async.commit_group;\n");
    };

    load_stage(0, 0);

    // per-lane ldmatrix offsets
    const int aro = ((lane >> 3) & 1) * 8 + (lane & 7);  // A row-in-frag
    const int aco = (lane >> 4) * 8;                     // A col-in-frag
    const int bro = lane & 7;                            // B row-in-frag (n)
    const int bco = ((lane >> 3) & 1) * 8;               // B col-in-frag (k)

    for (int kt = 0; kt < DIM / 32; kt++) {
        if (kt + 1 < DIM / 32) {
            load_stage((kt + 1) & 1, (kt + 1) * 32);
            asm volatile("cp.async.wait_group 1;\n");
        } else {
            asm volatile("cp.async.wait_group 0;\n");
        }
        __syncthreads();
        const int st = kt & 1;
#pragma unroll
        for (int kk = 0; kk < 32; kk += 16) {
            uint32_t a[4][4], b[4][2];
#pragma unroll
            for (int mf = 0; mf < 4; mf++) {
                unsigned addr = (unsigned)__cvta_generic_to_shared(
                    &As[st][(wm0 + mf * 16 + aro) * LDS + kk + aco]);
                asm volatile("ldmatrix.sync.aligned.m8n8.x4.shared.b16 {%0,%1,%2,%3}, [%4];\n"
                             : "=r"(a[mf][0]), "=r"(a[mf][1]), "=r"(a[mf][2]), "=r"(a[mf][3])
                             : "r"(addr));
            }
#pragma unroll
            for (int nf = 0; nf < 4; nf++) {
                unsigned addr = (unsigned)__cvta_generic_to_shared(
                    &Bs[st][(wn0 + nf * 8 + bro) * LDS + kk + bco]);
                asm volatile("ldmatrix.sync.aligned.m8n8.x2.shared.b16 {%0,%1}, [%2];\n"
                             : "=r"(b[nf][0]), "=r"(b[nf][1])
                             : "r"(addr));
            }
#pragma unroll
            for (int mf = 0; mf < 4; mf++)
#pragma unroll
                for (int nf = 0; nf < 4; nf++) {
                    asm volatile(
                        "mma.sync.aligned.m16n8k16.row.col.f32.bf16.bf16.f32 "
                        "{%0,%1,%2,%3}, {%4,%5,%6,%7}, {%8,%9}, {%0,%1,%2,%3};\n"
                        : "+f"(c[mf][nf][0]), "+f"(c[mf][nf][1]),
                          "+f"(c[mf][nf][2]), "+f"(c[mf][nf][3])
                        : "r"(a[mf][0]), "r"(a[mf][1]), "r"(a[mf][2]), "r"(a[mf][3]),
                          "r"(b[nf][0]), "r"(b[nf][1]));
                }
        }
        __syncthreads();
    }

    // fused epilogue: per-row sum(exp(logit)) and sum(logit) over this 128-col tile.
    // Deterministic: smem slot per (row, warp_n), no atomics.
#pragma unroll
    for (int mf = 0; mf < 4; mf++)
#pragma unroll
        for (int r = 0; r < 2; r++) {
            float se = 0.f, sl = 0.f;
#pragma unroll
            for (int nf = 0; nf < 4; nf++)
#pragma unroll
                for (int j = 0; j < 2; j++) {
                    float v = c[mf][nf][r * 2 + j];
                    se += __expf(v);
                    sl += v;
                }
            se += __shfl_xor_sync(0xffffffffu, se, 1);
            sl += __shfl_xor_sync(0xffffffffu, sl, 1);
            se += __shfl_xor_sync(0xffffffffu, se, 2);
            sl += __shfl_xor_sync(0xffffffffu, sl, 2);
            if ((lane & 3) == 0) {
                int row = wm0 + mf * 16 + r * 8 + (lane >> 2);
                redE[row][wn] = se;
                redL[row][wn] = sl;
            }
        }
    __syncthreads();
    if (tid < 128) {
        float e = redE[tid][0] + redE[tid][1] + redE[tid][2] + redE[tid][3];
        float l = redL[tid][0] + redL[tid][1] + redL[tid][2] + redL[tid][3];
        g_pExp[(size_t)ct * NROWS + m0 + tid] = e;
        g_pLog[(size_t)ct * NROWS + m0 + tid] = l;
    }
}

// ---------------- gathered target logit, fp32 exact path ----------------
// y is read as 32-bit words with a deterministic layout probe: labels are in
// [0, 32000), so an int64 little-endian layout has every odd 32-bit word == 0.
// Probability of that under an int32 layout: (1/32000)^4 — negligible.
__global__ void gatherdot_kernel(const float* __restrict__ x,
                                 const float* __restrict__ W,
                                 const int* __restrict__ y32) {
    int n = blockIdx.x, tid = threadIdx.x;  // 128 threads
    bool is64 = (y32[1] == 0) && (y32[3] == 0) && (y32[5] == 0) && (y32[7] == 0);
    int idx = is64 ? y32[2 * n] : y32[n];
    // clamp defensively (bad label would otherwise fault; result stays deterministic)
    if (idx < 0) idx = 0;
    if (idx >= VOCAB) idx = VOCAB - 1;
    const float* xr = x + (size_t)n * DIM;
    const float* wr = W + (size_t)idx * DIM;
    float s = 0.f;
    for (int d = tid; d < DIM; d += 128) s += xr[d] * wr[d];
#pragma unroll
    for (int o = 16; o; o >>= 1) s += __shfl_xor_sync(0xffffffffu, s, o);
    __shared__ float sm[4];
    if ((tid & 31) == 0) sm[tid >> 5] = s;
    __syncthreads();
    if (tid == 0) g_ly[n] = sm[0] + sm[1] + sm[2] + sm[3];
}

// ---------------- per-row reduce over column tiles ----------------
__global__ void rowreduce_kernel() {
    int n = blockIdx.x * 256 + threadIdx.x;  // 4096 rows
    float e = 0.f, l = 0.f;
    for (int t = 0; t < CTILES; t++) {
        e += g_pExp[(size_t)t * NROWS + n];
        l += g_pLog[(size_t)t * NROWS + n];
    }
    // per-row contribution: LSE - (1-s)*logit_y - (s/V)*sum_v logit
    g_rv[n] = logf(e) - (1.0f - SMOOTH) * g_ly[n] - (SMOOTH / (float)VOCAB) * l;
}

// ---------------- deterministic final scalar reduce ----------------
__global__ void final_kernel(float* __restrict__ out) {
    int tid = threadIdx.x;  // 1024 threads
    double s = 0.0;
    for (int i = tid; i < NROWS; i += 1024) s += (double)g_rv[i];
#pragma unroll
    for (int o = 16; o; o >>= 1) s += __shfl_xor_sync(0xffffffffu, s, o);
    __shared__ double sm[32];
    if ((tid & 31) == 0) sm[tid >> 5] = s;
    __syncthreads();
    if (tid < 32) {
        double v = sm[tid];
#pragma unroll
        for (int o = 16; o; o >>= 1) v += __shfl_xor_sync(0xffffffffu, v, o);
        if (tid == 0) out[0] = (float)(v / (double)NROWS);
    }
}

extern "C" void kernel_launch(void* const* d_in, const int* in_sizes, int n_in,
                              void* d_out, int out_size) {
    const float* x = nullptr;
    const float* W = nullptr;
    const int*   y = nullptr;
    for (int i = 0; i < n_in; i++) {
        if (in_sizes[i] == VOCAB * DIM)      W = (const float*)d_in[i];
        else if (in_sizes[i] == NROWS * DIM) x = (const float*)d_in[i];
        else if (in_sizes[i] == NROWS)       y = (const int*)d_in[i];
    }

    // gatherdot depends only on raw fp32 inputs — issue first so its gather
    // traffic overlaps the converts/GEMM instead of serializing after them.
    gatherdot_kernel<<<NROWS, 128>>>(x, W, y);
    cvt_x_kernel<<<(NROWS * DIM) / (256 * 4), 256>>>(x);
    cvt_w_kernel<<<(VOCAB * DIM) / (256 * 4), 256>>>(W);
    gemm_lse_kernel<<<dim3(CTILES, RTILES), 256>>>();
    rowreduce_kernel<<<NROWS / 256, 256>>>();
    final_kernel<<<1, 1024>>>((float*)d_out);
}